// round 16
// baseline (speedup 1.0000x reference)
#include <cuda_runtime.h>
#include <cuda_bf16.h>
#include <cuda_fp16.h>

#define NN 100000
#define DD 128
#define EE 1600000
#define NBLK 391   // ceil(NN/256)

// ---- scratch (__device__ globals per allocation-free rule) ----
__device__ unsigned g_xlh[(size_t)NN * 64]; // xl as half2 pairs (25.6 MB, L2-resident)
__device__ float    g_xr[(size_t)NN * DD];  // x @ W_r (streamed once)
__device__ int      g_srcs[EE];
__device__ int      g_cnt[NN];
__device__ int      g_off[NN + 1];
__device__ int      g_cur[NN];
__device__ int      g_bsum[512];
__device__ int      g_is64;
__device__ int      g_wk;                   // k_fused work-queue counter
// W pre-packed into bf16 mma-fragment layout: [ks(8)][j(32)][lane(32)][2] u32
__device__ unsigned g_wbh[16384];   // 64 KB hi component
__device__ unsigned g_wbl[16384];   // 64 KB lo component

__device__ __forceinline__ unsigned pkbf(float a, float b, float* ra, float* rb) {
    __nv_bfloat16 ha = __float2bfloat16(a), hb = __float2bfloat16(b);
    *ra = a - __bfloat162float(ha);
    *rb = b - __bfloat162float(hb);
    return (unsigned)__bfloat16_as_ushort(ha) |
           ((unsigned)__bfloat16_as_ushort(hb) << 16);
}
__device__ __forceinline__ unsigned pkbf2(float a, float b) {
    return (unsigned)__bfloat16_as_ushort(__float2bfloat16(a)) |
           ((unsigned)__bfloat16_as_ushort(__float2bfloat16(b)) << 16);
}
__device__ __forceinline__ void mma_bf16(float* c, const unsigned* a,
                                         unsigned b0, unsigned b1) {
    asm volatile(
        "mma.sync.aligned.m16n8k16.row.col.f32.bf16.bf16.f32 "
        "{%0,%1,%2,%3}, {%4,%5,%6,%7}, {%8,%9}, {%0,%1,%2,%3};"
        : "+f"(c[0]), "+f"(c[1]), "+f"(c[2]), "+f"(c[3])
        : "r"(a[0]), "r"(a[1]), "r"(a[2]), "r"(a[3]), "r"(b0), "r"(b1));
}

// ---------------------------------------------------------------------------
// K0: zero degree counters + work counter + detect edge dtype.
// ---------------------------------------------------------------------------
__global__ void k_zero(const int* __restrict__ ei_raw) {
    if (blockIdx.x == 0 && threadIdx.x == 0) {
        int all_zero = 1;
        for (int k = 0; k < 128; k++)
            if (ei_raw[2 * k + 1] != 0) { all_zero = 0; break; }
        g_is64 = all_zero;
        g_wk = 0;
    }
    for (int i = blockIdx.x * blockDim.x + threadIdx.x; i < NN;
         i += gridDim.x * blockDim.x)
        g_cnt[i] = 0;
}

__global__ void k_hist(const void* __restrict__ ei_raw, int E) {
    int is64 = g_is64;
    const long long* e64 = (const long long*)ei_raw;
    const int*       e32 = (const int*)ei_raw;
    for (int e = blockIdx.x * blockDim.x + threadIdx.x; e < E;
         e += gridDim.x * blockDim.x) {
        int d = is64 ? (int)__ldcs(&e64[E + e]) : __ldcs(&e32[E + e]);
        d = min(max(d, 0), NN - 1);
        atomicAdd(&g_cnt[d], 1);
    }
}

// ---------------------------------------------------------------------------
// pre-split + pre-pack W into per-lane bf16 fragment layout.
// ---------------------------------------------------------------------------
__global__ void k_prepw(const float* __restrict__ Wl,
                        const float* __restrict__ Wr) {
    int i = blockIdx.x * 256 + threadIdx.x;  // 8192 = 8ks * 32j * 32lane
    int lane = i & 31, j = (i >> 5) & 31, ks = i >> 10;
    int g = lane >> 2, t = lane & 3;
    int nc = j * 8 + g;
    const float* W = (nc < 128) ? Wl : Wr;
    int n = nc & 127;
    int k0 = ks * 16 + 2 * t;
    float w00 = W[(size_t)k0 * 128 + n];
    float w01 = W[(size_t)(k0 + 1) * 128 + n];
    float w10 = W[(size_t)(k0 + 8) * 128 + n];
    float w11 = W[(size_t)(k0 + 9) * 128 + n];
    float r0, r1, r2, r3;
    unsigned h0 = pkbf(w00, w01, &r0, &r1);
    unsigned h1 = pkbf(w10, w11, &r2, &r3);
    g_wbh[2 * i]     = h0;
    g_wbh[2 * i + 1] = h1;
    g_wbl[2 * i]     = pkbf2(r0, r1);
    g_wbl[2 * i + 1] = pkbf2(r2, r3);
}

// ---------------------------------------------------------------------------
// tensor dual GEMM via mma.sync bf16 m16n8k16, 3-way split (R13-proven):
// M=64 x N=256 tile, 8 warps, per-warp B LDG with double-buffer prefetch.
// ---------------------------------------------------------------------------
#define SA_STR 68   // u32 stride: banks (4g+t) all distinct -> conflict-free

__global__ __launch_bounds__(256, 2)
void k_tc(const float* __restrict__ x, int n) {
    __shared__ unsigned sAh[64 * SA_STR];
    __shared__ unsigned sAl[64 * SA_STR];

    int tid  = threadIdx.x;
    int lane = tid & 31;
    int wid  = tid >> 5;
    int row0  = blockIdx.x * 64;
    int mrow0 = (wid & 1) * 32;        // warp row offset
    int jbase = (wid >> 1) * 8;        // warp n-chunk base (0,8,16,24)

    // ---- stage whole A tile: 64 rows x 128 k -> bf16 hi/lo kpairs ----
    {
        int row = tid >> 2;            // 0..63
        int t4  = tid & 3;             // kpair range [16*t4, 16*t4+16)
        const float4* xr = (const float4*)(x + (size_t)(row0 + row) * 128 + t4 * 32);
        bool ok = (row0 + row) < n;
#pragma unroll
        for (int q = 0; q < 8; q++) {
            float4 f = ok ? __ldcs(&xr[q]) : make_float4(0.f, 0.f, 0.f, 0.f);
            float r0, r1, r2, r3;
            unsigned h0 = pkbf(f.x, f.y, &r0, &r1);
            unsigned h1 = pkbf(f.z, f.w, &r2, &r3);
            int kp = t4 * 16 + q * 2;
            sAh[row * SA_STR + kp]     = h0;
            sAh[row * SA_STR + kp + 1] = h1;
            sAl[row * SA_STR + kp]     = pkbf2(r0, r1);
            sAl[row * SA_STR + kp + 1] = pkbf2(r2, r3);
        }
    }
    __syncthreads();

    float acc[2][8][4] = {};
    int g = lane >> 2, t = lane & 3;

    // B-fragment double buffer: index q = ks*8 + jj
    uint2 bh = ((const uint2*)g_wbh)[(jbase) * 32 + lane];
    uint2 bl = ((const uint2*)g_wbl)[(jbase) * 32 + lane];

#pragma unroll
    for (int ks = 0; ks < 8; ks++) {
        unsigned ah[2][4], al[2][4];
#pragma unroll
        for (int m = 0; m < 2; m++) {
            int r = mrow0 + m * 16 + g;
            int kp = ks * 8 + t;
            ah[m][0] = sAh[r * SA_STR + kp];
            ah[m][1] = sAh[(r + 8) * SA_STR + kp];
            ah[m][2] = sAh[r * SA_STR + kp + 4];
            ah[m][3] = sAh[(r + 8) * SA_STR + kp + 4];
            al[m][0] = sAl[r * SA_STR + kp];
            al[m][1] = sAl[(r + 8) * SA_STR + kp];
            al[m][2] = sAl[r * SA_STR + kp + 4];
            al[m][3] = sAl[(r + 8) * SA_STR + kp + 4];
        }
#pragma unroll
        for (int jj = 0; jj < 8; jj++) {
            uint2 cbh = bh, cbl = bl;
            // prefetch next (ks,jj) fragment while MMAs run
            int qn = ks * 8 + jj + 1;
            if (qn < 64) {
                int ks2 = qn >> 3, jj2 = qn & 7;
                int fidx = (ks2 * 32 + jbase + jj2) * 32 + lane;
                bh = ((const uint2*)g_wbh)[fidx];
                bl = ((const uint2*)g_wbl)[fidx];
            }
#pragma unroll
            for (int m = 0; m < 2; m++) {
                mma_bf16(acc[m][jj], ah[m], cbh.x, cbh.y);
                mma_bf16(acc[m][jj], al[m], cbh.x, cbh.y);
                mma_bf16(acc[m][jj], ah[m], cbl.x, cbl.y);
            }
        }
    }

#pragma unroll
    for (int m = 0; m < 2; m++) {
        int row  = row0 + mrow0 + m * 16 + g;
        int row8 = row + 8;
#pragma unroll
        for (int jj = 0; jj < 8; jj++) {
            int col = (jbase + jj) * 8 + 2 * t;
            if (col < 128) {
                __half2 h01 = __floats2half2_rn(acc[m][jj][0], acc[m][jj][1]);
                __half2 h23 = __floats2half2_rn(acc[m][jj][2], acc[m][jj][3]);
                if (row < n)
                    g_xlh[(size_t)row * 64 + (col >> 1)] = *(unsigned*)&h01;
                if (row8 < n)
                    g_xlh[(size_t)row8 * 64 + (col >> 1)] = *(unsigned*)&h23;
            } else {
                int cc = col & 127;
                if (row < n)
                    *(float2*)(g_xr + (size_t)row * 128 + cc) =
                        make_float2(acc[m][jj][0], acc[m][jj][1]);
                if (row8 < n)
                    *(float2*)(g_xr + (size_t)row8 * 128 + cc) =
                        make_float2(acc[m][jj][2], acc[m][jj][3]);
            }
        }
    }
}

// ---- 2-level exclusive scan of g_cnt -> g_off ----
__global__ void k_scan1() {
    __shared__ int s[256];
    int t = threadIdx.x;
    int i = blockIdx.x * 256 + t;
    int v = (i < NN) ? g_cnt[i] : 0;
    s[t] = v;
    __syncthreads();
#pragma unroll
    for (int d = 1; d < 256; d <<= 1) {
        int add = (t >= d) ? s[t - d] : 0;
        __syncthreads();
        s[t] += add;
        __syncthreads();
    }
    if (i < NN) g_off[i] = s[t] - v;
    if (t == 255) g_bsum[blockIdx.x] = s[255];
}

__global__ void k_scan2(int E) {
    __shared__ int s[512];
    int t = threadIdx.x;
    int v = (t < NBLK) ? g_bsum[t] : 0;
    s[t] = v;
    __syncthreads();
#pragma unroll
    for (int d = 1; d < 512; d <<= 1) {
        int add = (t >= d) ? s[t - d] : 0;
        __syncthreads();
        s[t] += add;
        __syncthreads();
    }
    if (t < NBLK) g_bsum[t] = s[t] - v;
    if (t == 0) g_off[NN] = E;
}

__global__ void k_scan3() {
    for (int i = blockIdx.x * blockDim.x + threadIdx.x; i < NN;
         i += gridDim.x * blockDim.x) {
        int o = g_off[i] + g_bsum[i >> 8];
        g_off[i] = o;
        g_cur[i] = o;
    }
}

__global__ void k_scatter(const void* __restrict__ ei_raw, int E) {
    int is64 = g_is64;
    const long long* e64 = (const long long*)ei_raw;
    const int*       e32 = (const int*)ei_raw;
    for (int e = blockIdx.x * blockDim.x + threadIdx.x; e < E;
         e += gridDim.x * blockDim.x) {
        int s, d;
        if (is64) { s = (int)__ldcs(&e64[e]); d = (int)__ldcs(&e64[E + e]); }
        else      { s = __ldcs(&e32[e]);      d = __ldcs(&e32[E + e]); }
        s = min(max(s, 0), NN - 1);
        d = min(max(d, 0), NN - 1);
        int pos = atomicAdd(&g_cur[d], 1);
        __stcs(&g_srcs[pos], s);
    }
}

// ---------------------------------------------------------------------------
// fused score + softmax + aggregate: PERSISTENT warps, BATCHED work queue
// (4 nodes per atomic) with counter PREFETCH (next batch grabbed before the
// current batch is processed -> atomic latency fully hidden, zero exposure).
// ---------------------------------------------------------------------------
__global__ void k_fused(float* __restrict__ out,
                        const float* __restrict__ att,
                        const float* __restrict__ bias, int n) {
    int lane = threadIdx.x & 31;

    float4 a4 = ((const float4*)att)[lane];
    float c1x = 0.6f * a4.x, c1y = 0.6f * a4.y, c1z = 0.6f * a4.z, c1w = 0.6f * a4.w;
    float c2x = 0.4f * a4.x, c2y = 0.4f * a4.y, c2z = 0.4f * a4.z, c2w = 0.4f * a4.w;
    float4 b4 = ((const float4*)bias)[lane];

    int base;
    if (lane == 0) base = atomicAdd(&g_wk, 4);
    base = __shfl_sync(0xffffffffu, base, 0);

    while (base < n) {
        // prefetch next batch NOW; atomic latency hides behind batch work
        int nextb;
        if (lane == 0) nextb = atomicAdd(&g_wk, 4);
        nextb = __shfl_sync(0xffffffffu, nextb, 0);

        int lim = min(base + 4, n);
        for (int node = base; node < lim; node++) {
            float4 xi = __ldcs(&((const float4*)(g_xr + (size_t)node * 128))[lane]);
            int beg = g_off[node];
            int end = g_off[node + 1];

            float4 acc = make_float4(0.f, 0.f, 0.f, 0.f);
            float den = 0.f;

            int p = beg;
            for (; p + 3 < end; p += 4) {
                int  si[4];
                uint2 xu[4];
#pragma unroll
                for (int u = 0; u < 4; u++) si[u] = __ldcs(&g_srcs[p + u]);
#pragma unroll
                for (int u = 0; u < 4; u++)
                    xu[u] = __ldg(&((const uint2*)g_xlh)[(size_t)si[u] * 32 + lane]);

                float4 xj[4];
                float sc[4];
#pragma unroll
                for (int u = 0; u < 4; u++) {
                    float2 f01 = __half22float2(*(__half2*)&xu[u].x);
                    float2 f23 = __half22float2(*(__half2*)&xu[u].y);
                    xj[u] = make_float4(f01.x, f01.y, f23.x, f23.y);
                    float v, s;
                    v = xi.x + xj[u].x; s  = c1x * v; s = fmaf(c2x, fabsf(v), s);
                    v = xi.y + xj[u].y; s = fmaf(c1y, v, s); s = fmaf(c2y, fabsf(v), s);
                    v = xi.z + xj[u].z; s = fmaf(c1z, v, s); s = fmaf(c2z, fabsf(v), s);
                    v = xi.w + xj[u].w; s = fmaf(c1w, v, s); s = fmaf(c2w, fabsf(v), s);
                    sc[u] = s;
                }
#pragma unroll
                for (int u = 0; u < 4; u++) sc[u] += __shfl_xor_sync(0xffffffffu, sc[u], 1, 8);
#pragma unroll
                for (int u = 0; u < 4; u++) sc[u] += __shfl_xor_sync(0xffffffffu, sc[u], 2, 8);
#pragma unroll
                for (int u = 0; u < 4; u++) sc[u] += __shfl_xor_sync(0xffffffffu, sc[u], 4, 8);

                float ex[4];
#pragma unroll
                for (int u = 0; u < 4; u++) ex[u] = __expf(sc[u]);

#pragma unroll
                for (int u = 0; u < 4; u++) {
                    den += ex[u];
                    acc.x = fmaf(ex[u], xj[u].x, acc.x);
                    acc.y = fmaf(ex[u], xj[u].y, acc.y);
                    acc.z = fmaf(ex[u], xj[u].z, acc.z);
                    acc.w = fmaf(ex[u], xj[u].w, acc.w);
                }
            }
            for (; p < end; p++) {
                int s0 = __ldcs(&g_srcs[p]);
                uint2 xu = __ldg(&((const uint2*)g_xlh)[(size_t)s0 * 32 + lane]);
                float2 f01 = __half22float2(*(__half2*)&xu.x);
                float2 f23 = __half22float2(*(__half2*)&xu.y);
                float4 xj0 = make_float4(f01.x, f01.y, f23.x, f23.y);
                float v, s;
                v = xi.x + xj0.x; s  = c1x * v; s = fmaf(c2x, fabsf(v), s);
                v = xi.y + xj0.y; s = fmaf(c1y, v, s); s = fmaf(c2y, fabsf(v), s);
                v = xi.z + xj0.z; s = fmaf(c1z, v, s); s = fmaf(c2z, fabsf(v), s);
                v = xi.w + xj0.w; s = fmaf(c1w, v, s); s = fmaf(c2w, fabsf(v), s);
                s += __shfl_xor_sync(0xffffffffu, s, 1, 8);
                s += __shfl_xor_sync(0xffffffffu, s, 2, 8);
                s += __shfl_xor_sync(0xffffffffu, s, 4, 8);
                float ex0 = __expf(s);
                den += ex0;
                acc.x = fmaf(ex0, xj0.x, acc.x);
                acc.y = fmaf(ex0, xj0.y, acc.y);
                acc.z = fmaf(ex0, xj0.z, acc.z);
                acc.w = fmaf(ex0, xj0.w, acc.w);
            }

            float invd = 1.f / (den + 1e-16f);
            float4 o;
            o.x = fmaf(acc.x, invd, b4.x);
            o.y = fmaf(acc.y, invd, b4.y);
            o.z = fmaf(acc.z, invd, b4.z);
            o.w = fmaf(acc.w, invd, b4.w);
            __stcs(&((float4*)(out + (size_t)node * 128))[lane], o);
        }
        base = nextb;
    }
}

extern "C" void kernel_launch(void* const* d_in, const int* in_sizes, int n_in,
                              void* d_out, int out_size) {
    const float* x    = (const float*)d_in[0];
    const void*  ei   = d_in[1];
    const float* Wl   = (const float*)d_in[2];
    const float* Wr   = (const float*)d_in[3];
    const float* att  = (const float*)d_in[4];
    const float* bias = (const float*)d_in[5];
    float*       out  = (float*)d_out;

    int n = in_sizes[0] / DD;   // 100000
    int E = in_sizes[1] / 2;    // 1600000

    // Fork-join: GEMM branch (s2) concurrent with edge-CSR branch (stream 0).
    cudaStream_t s2;
    cudaEvent_t evFork, evJoin;
    cudaStreamCreateWithFlags(&s2, cudaStreamNonBlocking);
    cudaEventCreateWithFlags(&evFork, cudaEventDisableTiming);
    cudaEventCreateWithFlags(&evJoin, cudaEventDisableTiming);

    cudaEventRecord(evFork, 0);
    cudaStreamWaitEvent(s2, evFork, 0);

    k_zero   <<<256, 256>>>((const int*)ei);
    k_hist   <<<2048, 256>>>(ei, E);
    k_prepw  <<<32, 256, 0, s2>>>(Wl, Wr);
    k_tc     <<<(n + 63) / 64, 256, 0, s2>>>(x, n);
    cudaEventRecord(evJoin, s2);

    k_scan1  <<<NBLK, 256>>>();
    k_scan2  <<<1, 512>>>(E);
    k_scan3  <<<256, 256>>>();
    k_scatter<<<2048, 256>>>(ei, E);

    cudaStreamWaitEvent(0, evJoin, 0);
    k_fused  <<<1184, 256>>>(out, att, bias, n);  // persistent, batched queue
}

// round 17
// speedup vs baseline: 1.0692x; 1.0692x over previous
#include <cuda_runtime.h>
#include <cuda_bf16.h>
#include <cuda_fp16.h>

#define NN 100000
#define DD 128
#define EE 1600000
#define NBLK 391   // ceil(NN/256)

// ---- scratch (__device__ globals per allocation-free rule) ----
__device__ unsigned g_xlh[(size_t)NN * 64]; // xl as half2 pairs (25.6 MB, L2-resident)
__device__ float    g_xr[(size_t)NN * DD];  // x @ W_r (streamed once)
__device__ int      g_srcs[EE];
__device__ int      g_cnt[NN];
__device__ int      g_off[NN + 1];
__device__ int      g_cur[NN];
__device__ int      g_bsum[512];
__device__ int      g_is64;
// W pre-packed into bf16 mma-fragment layout: [ks(8)][j(32)][lane(32)][2] u32
__device__ unsigned g_wbh[16384];   // 64 KB hi component
__device__ unsigned g_wbl[16384];   // 64 KB lo component

__device__ __forceinline__ unsigned pkbf(float a, float b, float* ra, float* rb) {
    __nv_bfloat16 ha = __float2bfloat16(a), hb = __float2bfloat16(b);
    *ra = a - __bfloat162float(ha);
    *rb = b - __bfloat162float(hb);
    return (unsigned)__bfloat16_as_ushort(ha) |
           ((unsigned)__bfloat16_as_ushort(hb) << 16);
}
__device__ __forceinline__ unsigned pkbf2(float a, float b) {
    return (unsigned)__bfloat16_as_ushort(__float2bfloat16(a)) |
           ((unsigned)__bfloat16_as_ushort(__float2bfloat16(b)) << 16);
}
__device__ __forceinline__ void mma_bf16(float* c, const unsigned* a,
                                         unsigned b0, unsigned b1) {
    asm volatile(
        "mma.sync.aligned.m16n8k16.row.col.f32.bf16.bf16.f32 "
        "{%0,%1,%2,%3}, {%4,%5,%6,%7}, {%8,%9}, {%0,%1,%2,%3};"
        : "+f"(c[0]), "+f"(c[1]), "+f"(c[2]), "+f"(c[3])
        : "r"(a[0]), "r"(a[1]), "r"(a[2]), "r"(a[3]), "r"(b0), "r"(b1));
}

// ---------------------------------------------------------------------------
// K0: zero degree counters + detect edge dtype (int64 vs int32).
// ---------------------------------------------------------------------------
__global__ void k_zero(const int* __restrict__ ei_raw) {
    if (blockIdx.x == 0 && threadIdx.x == 0) {
        int all_zero = 1;
        for (int k = 0; k < 128; k++)
            if (ei_raw[2 * k + 1] != 0) { all_zero = 0; break; }
        g_is64 = all_zero;
    }
    for (int i = blockIdx.x * blockDim.x + threadIdx.x; i < NN;
         i += gridDim.x * blockDim.x)
        g_cnt[i] = 0;
}

__global__ void k_hist(const void* __restrict__ ei_raw, int E) {
    int is64 = g_is64;
    const long long* e64 = (const long long*)ei_raw;
    const int*       e32 = (const int*)ei_raw;
    for (int e = blockIdx.x * blockDim.x + threadIdx.x; e < E;
         e += gridDim.x * blockDim.x) {
        int d = is64 ? (int)__ldcs(&e64[E + e]) : __ldcs(&e32[E + e]);
        d = min(max(d, 0), NN - 1);
        atomicAdd(&g_cnt[d], 1);
    }
}

// ---------------------------------------------------------------------------
// pre-split + pre-pack W into per-lane bf16 fragment layout.
// ---------------------------------------------------------------------------
__global__ void k_prepw(const float* __restrict__ Wl,
                        const float* __restrict__ Wr) {
    int i = blockIdx.x * 256 + threadIdx.x;  // 8192 = 8ks * 32j * 32lane
    int lane = i & 31, j = (i >> 5) & 31, ks = i >> 10;
    int g = lane >> 2, t = lane & 3;
    int nc = j * 8 + g;
    const float* W = (nc < 128) ? Wl : Wr;
    int n = nc & 127;
    int k0 = ks * 16 + 2 * t;
    float w00 = W[(size_t)k0 * 128 + n];
    float w01 = W[(size_t)(k0 + 1) * 128 + n];
    float w10 = W[(size_t)(k0 + 8) * 128 + n];
    float w11 = W[(size_t)(k0 + 9) * 128 + n];
    float r0, r1, r2, r3;
    unsigned h0 = pkbf(w00, w01, &r0, &r1);
    unsigned h1 = pkbf(w10, w11, &r2, &r3);
    g_wbh[2 * i]     = h0;
    g_wbh[2 * i + 1] = h1;
    g_wbl[2 * i]     = pkbf2(r0, r1);
    g_wbl[2 * i + 1] = pkbf2(r2, r3);
}

// ---------------------------------------------------------------------------
// tensor dual GEMM via mma.sync bf16 m16n8k16, 3-way split (R13-proven):
// M=64 x N=256 tile, 8 warps, per-warp B LDG with double-buffer prefetch.
// ---------------------------------------------------------------------------
#define SA_STR 68   // u32 stride: banks (4g+t) all distinct -> conflict-free

__global__ __launch_bounds__(256, 2)
void k_tc(const float* __restrict__ x, int n) {
    __shared__ unsigned sAh[64 * SA_STR];
    __shared__ unsigned sAl[64 * SA_STR];

    int tid  = threadIdx.x;
    int lane = tid & 31;
    int wid  = tid >> 5;
    int row0  = blockIdx.x * 64;
    int mrow0 = (wid & 1) * 32;        // warp row offset
    int jbase = (wid >> 1) * 8;        // warp n-chunk base (0,8,16,24)

    // ---- stage whole A tile: 64 rows x 128 k -> bf16 hi/lo kpairs ----
    {
        int row = tid >> 2;            // 0..63
        int t4  = tid & 3;             // kpair range [16*t4, 16*t4+16)
        const float4* xr = (const float4*)(x + (size_t)(row0 + row) * 128 + t4 * 32);
        bool ok = (row0 + row) < n;
#pragma unroll
        for (int q = 0; q < 8; q++) {
            float4 f = ok ? __ldcs(&xr[q]) : make_float4(0.f, 0.f, 0.f, 0.f);
            float r0, r1, r2, r3;
            unsigned h0 = pkbf(f.x, f.y, &r0, &r1);
            unsigned h1 = pkbf(f.z, f.w, &r2, &r3);
            int kp = t4 * 16 + q * 2;
            sAh[row * SA_STR + kp]     = h0;
            sAh[row * SA_STR + kp + 1] = h1;
            sAl[row * SA_STR + kp]     = pkbf2(r0, r1);
            sAl[row * SA_STR + kp + 1] = pkbf2(r2, r3);
        }
    }
    __syncthreads();

    float acc[2][8][4] = {};
    int g = lane >> 2, t = lane & 3;

    // B-fragment double buffer: index q = ks*8 + jj
    uint2 bh = ((const uint2*)g_wbh)[(jbase) * 32 + lane];
    uint2 bl = ((const uint2*)g_wbl)[(jbase) * 32 + lane];

#pragma unroll
    for (int ks = 0; ks < 8; ks++) {
        unsigned ah[2][4], al[2][4];
#pragma unroll
        for (int m = 0; m < 2; m++) {
            int r = mrow0 + m * 16 + g;
            int kp = ks * 8 + t;
            ah[m][0] = sAh[r * SA_STR + kp];
            ah[m][1] = sAh[(r + 8) * SA_STR + kp];
            ah[m][2] = sAh[r * SA_STR + kp + 4];
            ah[m][3] = sAh[(r + 8) * SA_STR + kp + 4];
            al[m][0] = sAl[r * SA_STR + kp];
            al[m][1] = sAl[(r + 8) * SA_STR + kp];
            al[m][2] = sAl[r * SA_STR + kp + 4];
            al[m][3] = sAl[(r + 8) * SA_STR + kp + 4];
        }
#pragma unroll
        for (int jj = 0; jj < 8; jj++) {
            uint2 cbh = bh, cbl = bl;
            // prefetch next (ks,jj) fragment while MMAs run
            int qn = ks * 8 + jj + 1;
            if (qn < 64) {
                int ks2 = qn >> 3, jj2 = qn & 7;
                int fidx = (ks2 * 32 + jbase + jj2) * 32 + lane;
                bh = ((const uint2*)g_wbh)[fidx];
                bl = ((const uint2*)g_wbl)[fidx];
            }
#pragma unroll
            for (int m = 0; m < 2; m++) {
                mma_bf16(acc[m][jj], ah[m], cbh.x, cbh.y);
                mma_bf16(acc[m][jj], al[m], cbh.x, cbh.y);
                mma_bf16(acc[m][jj], ah[m], cbl.x, cbl.y);
            }
        }
    }

#pragma unroll
    for (int m = 0; m < 2; m++) {
        int row  = row0 + mrow0 + m * 16 + g;
        int row8 = row + 8;
#pragma unroll
        for (int jj = 0; jj < 8; jj++) {
            int col = (jbase + jj) * 8 + 2 * t;
            if (col < 128) {
                __half2 h01 = __floats2half2_rn(acc[m][jj][0], acc[m][jj][1]);
                __half2 h23 = __floats2half2_rn(acc[m][jj][2], acc[m][jj][3]);
                if (row < n)
                    g_xlh[(size_t)row * 64 + (col >> 1)] = *(unsigned*)&h01;
                if (row8 < n)
                    g_xlh[(size_t)row8 * 64 + (col >> 1)] = *(unsigned*)&h23;
            } else {
                int cc = col & 127;
                if (row < n)
                    *(float2*)(g_xr + (size_t)row * 128 + cc) =
                        make_float2(acc[m][jj][0], acc[m][jj][1]);
                if (row8 < n)
                    *(float2*)(g_xr + (size_t)row8 * 128 + cc) =
                        make_float2(acc[m][jj][2], acc[m][jj][3]);
            }
        }
    }
}

// ---- 2-level exclusive scan of g_cnt -> g_off ----
__global__ void k_scan1() {
    __shared__ int s[256];
    int t = threadIdx.x;
    int i = blockIdx.x * 256 + t;
    int v = (i < NN) ? g_cnt[i] : 0;
    s[t] = v;
    __syncthreads();
#pragma unroll
    for (int d = 1; d < 256; d <<= 1) {
        int add = (t >= d) ? s[t - d] : 0;
        __syncthreads();
        s[t] += add;
        __syncthreads();
    }
    if (i < NN) g_off[i] = s[t] - v;
    if (t == 255) g_bsum[blockIdx.x] = s[255];
}

__global__ void k_scan2(int E) {
    __shared__ int s[512];
    int t = threadIdx.x;
    int v = (t < NBLK) ? g_bsum[t] : 0;
    s[t] = v;
    __syncthreads();
#pragma unroll
    for (int d = 1; d < 512; d <<= 1) {
        int add = (t >= d) ? s[t - d] : 0;
        __syncthreads();
        s[t] += add;
        __syncthreads();
    }
    if (t < NBLK) g_bsum[t] = s[t] - v;
    if (t == 0) g_off[NN] = E;
}

__global__ void k_scan3() {
    for (int i = blockIdx.x * blockDim.x + threadIdx.x; i < NN;
         i += gridDim.x * blockDim.x) {
        int o = g_off[i] + g_bsum[i >> 8];
        g_off[i] = o;
        g_cur[i] = o;
    }
}

__global__ void k_scatter(const void* __restrict__ ei_raw, int E) {
    int is64 = g_is64;
    const long long* e64 = (const long long*)ei_raw;
    const int*       e32 = (const int*)ei_raw;
    for (int e = blockIdx.x * blockDim.x + threadIdx.x; e < E;
         e += gridDim.x * blockDim.x) {
        int s, d;
        if (is64) { s = (int)__ldcs(&e64[e]); d = (int)__ldcs(&e64[E + e]); }
        else      { s = __ldcs(&e32[e]);      d = __ldcs(&e32[E + e]); }
        s = min(max(s, 0), NN - 1);
        d = min(max(d, 0), NN - 1);
        int pos = atomicAdd(&g_cur[d], 1);
        __stcs(&g_srcs[pos], s);
    }
}

// ---------------------------------------------------------------------------
// fused score + softmax + aggregate: STATIC one-warp-per-node (R13-proven)
// + software-pipelined edge loop: next 4 edges' indices+rows prefetched while
// computing the current 4 (hides the srcs->xlh L2 dependency chain).
// Butterfly head reductions, branchless all-lane exp.
// ---------------------------------------------------------------------------
__global__ void k_fused(float* __restrict__ out,
                        const float* __restrict__ att,
                        const float* __restrict__ bias, int n) {
    int node = (blockIdx.x * blockDim.x + threadIdx.x) >> 5;
    int lane = threadIdx.x & 31;
    if (node >= n) return;

    float4 a4 = ((const float4*)att)[lane];
    float c1x = 0.6f * a4.x, c1y = 0.6f * a4.y, c1z = 0.6f * a4.z, c1w = 0.6f * a4.w;
    float c2x = 0.4f * a4.x, c2y = 0.4f * a4.y, c2z = 0.4f * a4.z, c2w = 0.4f * a4.w;

    float4 xi = __ldcs(&((const float4*)(g_xr + (size_t)node * 128))[lane]);
    int beg = g_off[node];
    int end = g_off[node + 1];

    float4 acc = make_float4(0.f, 0.f, 0.f, 0.f);
    float den = 0.f;

    int p = beg;
    uint2 xu[4];
    bool have = (p + 3 < end);
    if (have) {
        int si[4];
#pragma unroll
        for (int u = 0; u < 4; u++) si[u] = __ldcs(&g_srcs[p + u]);
#pragma unroll
        for (int u = 0; u < 4; u++)
            xu[u] = __ldg(&((const uint2*)g_xlh)[(size_t)si[u] * 32 + lane]);
    }
    while (have) {
        // prefetch the NEXT 4 edges before computing on the current 4
        bool haveN = (p + 7 < end);
        uint2 xuN[4];
        if (haveN) {
            int siN[4];
#pragma unroll
            for (int u = 0; u < 4; u++) siN[u] = __ldcs(&g_srcs[p + 4 + u]);
#pragma unroll
            for (int u = 0; u < 4; u++)
                xuN[u] = __ldg(&((const uint2*)g_xlh)[(size_t)siN[u] * 32 + lane]);
        }

        float4 xj[4];
        float sc[4];
#pragma unroll
        for (int u = 0; u < 4; u++) {
            float2 f01 = __half22float2(*(__half2*)&xu[u].x);
            float2 f23 = __half22float2(*(__half2*)&xu[u].y);
            xj[u] = make_float4(f01.x, f01.y, f23.x, f23.y);
            float v, s;
            v = xi.x + xj[u].x; s  = c1x * v; s = fmaf(c2x, fabsf(v), s);
            v = xi.y + xj[u].y; s = fmaf(c1y, v, s); s = fmaf(c2y, fabsf(v), s);
            v = xi.z + xj[u].z; s = fmaf(c1z, v, s); s = fmaf(c2z, fabsf(v), s);
            v = xi.w + xj[u].w; s = fmaf(c1w, v, s); s = fmaf(c2w, fabsf(v), s);
            sc[u] = s;
        }
#pragma unroll
        for (int u = 0; u < 4; u++) sc[u] += __shfl_xor_sync(0xffffffffu, sc[u], 1, 8);
#pragma unroll
        for (int u = 0; u < 4; u++) sc[u] += __shfl_xor_sync(0xffffffffu, sc[u], 2, 8);
#pragma unroll
        for (int u = 0; u < 4; u++) sc[u] += __shfl_xor_sync(0xffffffffu, sc[u], 4, 8);

        float ex[4];
#pragma unroll
        for (int u = 0; u < 4; u++) ex[u] = __expf(sc[u]);

#pragma unroll
        for (int u = 0; u < 4; u++) {
            den += ex[u];
            acc.x = fmaf(ex[u], xj[u].x, acc.x);
            acc.y = fmaf(ex[u], xj[u].y, acc.y);
            acc.z = fmaf(ex[u], xj[u].z, acc.z);
            acc.w = fmaf(ex[u], xj[u].w, acc.w);
        }

        p += 4;
        have = haveN;
#pragma unroll
        for (int u = 0; u < 4; u++) xu[u] = xuN[u];
    }
    for (; p < end; p++) {
        int s0 = __ldcs(&g_srcs[p]);
        uint2 xs = __ldg(&((const uint2*)g_xlh)[(size_t)s0 * 32 + lane]);
        float2 f01 = __half22float2(*(__half2*)&xs.x);
        float2 f23 = __half22float2(*(__half2*)&xs.y);
        float4 xj0 = make_float4(f01.x, f01.y, f23.x, f23.y);
        float v, s;
        v = xi.x + xj0.x; s  = c1x * v; s = fmaf(c2x, fabsf(v), s);
        v = xi.y + xj0.y; s = fmaf(c1y, v, s); s = fmaf(c2y, fabsf(v), s);
        v = xi.z + xj0.z; s = fmaf(c1z, v, s); s = fmaf(c2z, fabsf(v), s);
        v = xi.w + xj0.w; s = fmaf(c1w, v, s); s = fmaf(c2w, fabsf(v), s);
        s += __shfl_xor_sync(0xffffffffu, s, 1, 8);
        s += __shfl_xor_sync(0xffffffffu, s, 2, 8);
        s += __shfl_xor_sync(0xffffffffu, s, 4, 8);
        float ex0 = __expf(s);
        den += ex0;
        acc.x = fmaf(ex0, xj0.x, acc.x);
        acc.y = fmaf(ex0, xj0.y, acc.y);
        acc.z = fmaf(ex0, xj0.z, acc.z);
        acc.w = fmaf(ex0, xj0.w, acc.w);
    }

    float invd = 1.f / (den + 1e-16f);
    float4 b4 = ((const float4*)bias)[lane];
    float4 o;
    o.x = fmaf(acc.x, invd, b4.x);
    o.y = fmaf(acc.y, invd, b4.y);
    o.z = fmaf(acc.z, invd, b4.z);
    o.w = fmaf(acc.w, invd, b4.w);
    __stcs(&((float4*)(out + (size_t)node * 128))[lane], o);
}

extern "C" void kernel_launch(void* const* d_in, const int* in_sizes, int n_in,
                              void* d_out, int out_size) {
    const float* x    = (const float*)d_in[0];
    const void*  ei   = d_in[1];
    const float* Wl   = (const float*)d_in[2];
    const float* Wr   = (const float*)d_in[3];
    const float* att  = (const float*)d_in[4];
    const float* bias = (const float*)d_in[5];
    float*       out  = (float*)d_out;

    int n = in_sizes[0] / DD;   // 100000
    int E = in_sizes[1] / 2;    // 1600000

    // Fork-join: GEMM branch (s2) concurrent with edge-CSR branch (stream 0).
    // k_tc kept at launch idx 3 (the one ncu profiles).
    cudaStream_t s2;
    cudaEvent_t evFork, evJoin;
    cudaStreamCreateWithFlags(&s2, cudaStreamNonBlocking);
    cudaEventCreateWithFlags(&evFork, cudaEventDisableTiming);
    cudaEventCreateWithFlags(&evJoin, cudaEventDisableTiming);

    cudaEventRecord(evFork, 0);
    cudaStreamWaitEvent(s2, evFork, 0);

    k_zero   <<<256, 256>>>((const int*)ei);              // idx 0
    k_prepw  <<<32, 256, 0, s2>>>(Wl, Wr);                // idx 1
    k_hist   <<<2048, 256>>>(ei, E);                      // idx 2
    k_tc     <<<(n + 63) / 64, 256, 0, s2>>>(x, n);       // idx 3 (profiled)
    cudaEventRecord(evJoin, s2);

    k_scan1  <<<NBLK, 256>>>();
    k_scan2  <<<1, 512>>>(E);
    k_scan3  <<<256, 256>>>();
    k_scatter<<<2048, 256>>>(ei, E);

    cudaStreamWaitEvent(0, evJoin, 0);
    k_fused  <<<(n * 32 + 255) / 256, 256>>>(out, att, bias, n);
}